// round 9
// baseline (speedup 1.0000x reference)
#include <cuda_runtime.h>
#include <math.h>
#include <stdint.h>

// Problem constants
#define BGRAPH   256
#define M_ATOMS  48
#define NNODES   (BGRAPH * M_ATOMS)          // 12288
#define GRAPH_E  (M_ATOMS * (M_ATOMS - 1))   // 2256
#define EDGES    (BGRAPH * GRAPH_E)          // 577536
#define KRBF     32
#define NSH      25
#define FEAT     (KRBF + NSH)                // 57
#define HS       128
#define CUTOFF_INV (1.0f / 15.0f)

// Output layout (floats): feat [E,57] | node_emb [N,128] | edge_index [2,E] | transpose_index [E]
#define EMB_OFF  ((size_t)EDGES * FEAT)                 // 32,919,552
#define EI_OFF   (EMB_OFF + (size_t)NNODES * HS)        // 34,492,416
#define TR_OFF   (EI_OFF + 2 * (size_t)EDGES)           // 35,647,488

#define BLOCK    64
#define EDGE_BLOCKS (EDGES / BLOCK)                      // 9024
#define EMB_BLOCKS  ((NNODES * 32) / BLOCK)              // 6144
#define TOTAL_BLOCKS (EDGE_BLOCKS + EMB_BLOCKS)          // 15168

// L2 residency: pin ~101 MB of the 145.8 MB output (feat blocks < PIN, in
// 64-edge units: 6000 * 14592 B = 87.6 MB, + emb 6.3 MB + idx 6.9 MB).
#define PIN_FEAT_BLOCKS 6000

__device__ __forceinline__ uint32_t smem_u32(const void* p) {
    uint32_t a;
    asm("{ .reg .u64 t; cvta.to.shared.u64 t, %1; cvt.u32.u64 %0, t; }" : "=r"(a) : "l"(p));
    return a;
}
__device__ __forceinline__ uint64_t policy_evict_last() {
    uint64_t pol;
    asm("createpolicy.fractional.L2::evict_last.b64 %0, 1.0;" : "=l"(pol));
    return pol;
}
__device__ __forceinline__ uint64_t policy_evict_first() {
    uint64_t pol;
    asm("createpolicy.fractional.L2::evict_first.b64 %0, 1.0;" : "=l"(pol));
    return pol;
}
__device__ __forceinline__ void stg_hint(float* p, float v, uint64_t pol) {
    asm volatile("st.global.L2::cache_hint.f32 [%0], %1, %2;"
                 :: "l"(p), "f"(v), "l"(pol) : "memory");
}
__device__ __forceinline__ void stg4_hint(float4* p, float4 v, uint64_t pol) {
    asm volatile("st.global.L2::cache_hint.v4.f32 [%0], {%1,%2,%3,%4}, %5;"
                 :: "l"(p), "f"(v.x), "f"(v.y), "f"(v.z), "f"(v.w), "l"(pol) : "memory");
}

// ---------------------------------------------------------------------------
// Fused kernel, 64-thread CTAs (higher CTA-level concurrency, smaller
// TMA-wait tail granularity).
//  blocks [0, 9024): 1 thread = 1 edge -> smem tile [64][57], one
//    cp.async.bulk (14592 B) per block with L2 eviction hint.
//  blocks [9024, 15168): embedding gather, 1 thread = 1 float4.
// ---------------------------------------------------------------------------
__global__ void __launch_bounds__(BLOCK) fused_kernel(
    const float*  __restrict__ pos,
    const int*    __restrict__ an,
    const float4* __restrict__ table4,
    const float*  __restrict__ alpha,
    float* __restrict__ out)
{
    __shared__ __align__(16) float tile[BLOCK * FEAT];

    if (blockIdx.x >= EDGE_BLOCKS) {
        const int i = (blockIdx.x - EDGE_BLOCKS) * BLOCK + threadIdx.x; // < NNODES*32
        const int n = i >> 5;
        const int c = i & 31;
        float4* out4 = (float4*)(out + EMB_OFF);
        stg4_hint(out4 + i, table4[an[n] * 32 + c], policy_evict_last());
        return;
    }

    const int e = blockIdx.x * BLOCK + threadIdx.x;    // grid sized exactly

    // ---- index math ----
    const int g = e / GRAPH_E;
    const int t = e - g * GRAPH_E;
    const int s = t / (M_ATOMS - 1);
    const int k = t - s * (M_ATOMS - 1);
    const int d = k + (k >= s);
    const int src = g * M_ATOMS + s;
    const int dst = g * M_ATOMS + d;
    const int tr  = g * GRAPH_E + d * (M_ATOMS - 1) + s - (d < s);

    // ---- pos prefetch ----
    const float dx0 = __ldg(pos + dst * 3 + 0);
    const float dy0 = __ldg(pos + dst * 3 + 1);
    const float dz0 = __ldg(pos + dst * 3 + 2);
    const float sx0 = __ldg(pos + src * 3 + 0);
    const float sy0 = __ldg(pos + src * 3 + 1);
    const float sz0 = __ldg(pos + src * 3 + 2);

    // ---- index outputs (coalesced, pinned region) ----
    {
        const uint64_t pol = policy_evict_last();
        stg_hint(out + EI_OFF + e,         (float)dst, pol);
        stg_hint(out + EI_OFF + EDGES + e, (float)src, pol);
        stg_hint(out + TR_OFF + e,         (float)tr,  pol);
    }

    // ---- geometry ----
    const float ex = dx0 - sx0, ey = dy0 - sy0, ez = dz0 - sz0;
    float r2 = fmaxf(ex * ex + ey * ey + ez * ez, 1e-12f);
    const float rinv = rsqrtf(r2);          // MUFU.RSQ
    const float r    = r2 * rinv;
    const float x = ex * rinv, y = ey * rinv, z = ez * rinv;

    float* row = &tile[threadIdx.x * FEAT];

    // ---- cutoff ----
    const float rc  = r * CUTOFF_INV;
    const float rc2 = rc * rc;
    const float den = fmaxf((1.0f - rc) * (1.0f + rc), 1e-9f);
    const float fcut = (rc < 1.0f) ? __expf(-__fdividef(rc2, den)) : 0.0f;

    // ---- exponential Bernstein RBF: 4-way-split ratio recurrence ----
    // term(v) = fcut * C(31,v) * a^(31-v) * b^v with a = max(p,q) >= 1/2,
    // written ascending (a==p) or descending (a==q) by binomial symmetry.
    // Four independent chains over v, v+4, ... : serial depth 7 muls.
    const float aeff = 0.5f * alpha[0];
    const float xx = -aeff * r;
    const float p = __expf(xx);             // MUFU.EX2
    const float q = 1.0f - p;
    const float a = fmaxf(p, q);
    const float b = 1.0f - a;
    const float ratio  = __fdividef(b, a);  // MUFU.RCP + mul
    const float ratio2 = ratio * ratio;
    const float ratio4 = ratio2 * ratio2;

    const float a2 = a * a, a4 = a2 * a2, a8 = a4 * a4, a16 = a8 * a8;
    const float seed = a16 * a8 * a4 * a2 * a * fcut;   // fcut * a^31

    float t0 = seed;                                   // v=0
    float t1 = seed * (31.0f * ratio);                 // v=1
    float t2 = t1 * (15.0f * ratio);                   // v=2  (C ratio 30/2)
    float t3 = t2 * ((29.0f / 3.0f) * ratio);          // v=3

    const bool up = (p >= q);
    float* sp = row + (up ? 0 : 31);
    const int step = up ? 1 : -1;

    sp[0]        = t0;
    sp[step]     = t1;
    sp[step * 2] = t2;
    sp[step * 3] = t3;
#pragma unroll
    for (int v = 0; v < 28; v += 4) {
        // advance each chain by 4: C(31,v+4)/C(31,v)
        const float cA = ((float)((31 - v) * (30 - v)) * (float)((29 - v) * (28 - v))) /
                         ((float)((v + 1) * (v + 2)) * (float)((v + 3) * (v + 4)));
        const float cB = ((float)((30 - v) * (29 - v)) * (float)((28 - v) * (27 - v))) /
                         ((float)((v + 2) * (v + 3)) * (float)((v + 4) * (v + 5)));
        const float cC = ((float)((29 - v) * (28 - v)) * (float)((27 - v) * (26 - v))) /
                         ((float)((v + 3) * (v + 4)) * (float)((v + 5) * (v + 6)));
        const float cD = ((float)((28 - v) * (27 - v)) * (float)((26 - v) * (25 - v))) /
                         ((float)((v + 4) * (v + 5)) * (float)((v + 6) * (v + 7)));
        t0 *= ratio4 * cA;
        t1 *= ratio4 * cB;
        t2 *= ratio4 * cC;
        t3 *= ratio4 * cD;
        sp[step * (v + 4)] = t0;
        sp[step * (v + 5)] = t1;
        sp[step * (v + 6)] = t2;
        sp[step * (v + 7)] = t3;
    }

    // ---- real spherical harmonics, component-normalized, l <= 4 ----
    const float C2 = x * x - y * y,      S2 = 2.0f * x * y;
    const float C3 = C2 * x - S2 * y,    S3 = S2 * x + C2 * y;
    const float C4 = C3 * x - S3 * y,    S4 = S3 * x + C3 * y;
    const float z2 = z * z;

    const float q20 = 1.5f  * z2 - 0.5f;
    const float q30 = (2.5f * z2 - 1.5f) * z;
    const float q40 = (4.375f * z2 - 3.75f) * z2 + 0.375f;
    const float q31 = 7.5f  * z2 - 1.5f;
    const float q41 = (17.5f * z2 - 7.5f) * z;
    const float q42 = 52.5f * z2 - 7.5f;

    float* sh = row + KRBF;
    sh[0]  = 1.0f;
    sh[1]  = 1.7320508f * y;
    sh[2]  = 1.7320508f * z;
    sh[3]  = 1.7320508f * x;
    sh[4]  = 1.9364917f * S2;
    sh[5]  = 3.8729833f * y * z;
    sh[6]  = 2.2360680f * q20;
    sh[7]  = 3.8729833f * x * z;
    sh[8]  = 1.9364917f * C2;
    sh[9]  = 2.0916500f * S3;
    sh[10] = 5.1234756f * z * S2;
    sh[11] = 1.0801234f * q31 * y;
    sh[12] = 2.6457513f * q30;
    sh[13] = 1.0801234f * q31 * x;
    sh[14] = 5.1234756f * z * C2;
    sh[15] = 2.0916500f * C3;
    sh[16] = 2.2185299f * S4;
    sh[17] = 6.2749501f * z * S3;
    sh[18] = 0.2236068f * q42 * S2;
    sh[19] = 0.9486833f * q41 * y;
    sh[20] = 3.0f       * q40;
    sh[21] = 0.9486833f * q41 * x;
    sh[22] = 0.2236068f * q42 * C2;
    sh[23] = 6.2749501f * z * C3;
    sh[24] = 2.2185299f * C4;

    // ---- flush block tile (14592 B, contiguous smem AND global) ----
    __syncthreads();
    if (threadIdx.x == 0) {
        asm volatile("fence.proxy.async.shared::cta;" ::: "memory");
        float* gdst = out + (size_t)blockIdx.x * (BLOCK * FEAT);
        const uint32_t saddr = smem_u32(tile);
        const uint64_t pol = (blockIdx.x < PIN_FEAT_BLOCKS) ? policy_evict_last()
                                                            : policy_evict_first();
        asm volatile(
            "cp.async.bulk.global.shared::cta.bulk_group.L2::cache_hint [%0], [%1], %2, %3;"
            :: "l"(gdst), "r"(saddr), "r"(BLOCK * FEAT * 4), "l"(pol) : "memory");
        asm volatile("cp.async.bulk.commit_group;" ::: "memory");
        asm volatile("cp.async.bulk.wait_group.read 0;" ::: "memory");
    }
}

extern "C" void kernel_launch(void* const* d_in, const int* in_sizes, int n_in,
                              void* d_out, int out_size)
{
    const float* pos   = (const float*)d_in[0];
    const int*   an    = (const int*)d_in[1];
    const float* table = (const float*)d_in[2];
    const float* alpha = (const float*)d_in[3];
    float* out = (float*)d_out;

    fused_kernel<<<TOTAL_BLOCKS, BLOCK>>>(pos, an, (const float4*)table, alpha, out);
}

// round 11
// speedup vs baseline: 1.0625x; 1.0625x over previous
#include <cuda_runtime.h>
#include <math.h>
#include <stdint.h>

// Problem constants
#define BGRAPH   256
#define M_ATOMS  48
#define NNODES   (BGRAPH * M_ATOMS)          // 12288
#define GRAPH_E  (M_ATOMS * (M_ATOMS - 1))   // 2256
#define EDGES    (BGRAPH * GRAPH_E)          // 577536
#define KRBF     32
#define NSH      25
#define FEAT     (KRBF + NSH)                // 57
#define HS       128
#define CUTOFF_INV (1.0f / 15.0f)

// Output layout (floats): feat [E,57] | node_emb [N,128] | edge_index [2,E] | transpose_index [E]
#define EMB_OFF  ((size_t)EDGES * FEAT)                 // 32,919,552
#define EI_OFF   (EMB_OFF + (size_t)NNODES * HS)        // 34,492,416
#define TR_OFF   (EI_OFF + 2 * (size_t)EDGES)           // 35,647,488

// Edge side: warp-tiles of 32 edges, T tiles per warp, 2 warps per block.
#define TILES        (EDGES / 32)            // 18048
#define T_PER_WARP   4
#define WPB          2
#define EDGE_BLOCKS  (TILES / (WPB * T_PER_WARP))   // 2256
// Emb side: 64 threads * 4 float4 per block.
#define EMB_ITEMS    (NNODES * HS / 4)       // 393216 float4
#define EMB_BLOCKS   (EMB_ITEMS / (64 * 4))  // 1536
#define TOTAL_BLOCKS (EDGE_BLOCKS + EMB_BLOCKS)     // 3792

// L2 residency: pin same ~95 MB as R8. In 32-edge (7296 B) tile units:
// 11200 tiles * 7296 B = 81.7 MB + emb 6.3 MB + idx 6.9 MB.
#define PIN_TILES 11200

#define TILE_F  (32 * FEAT)                  // 1824 floats = 7296 B

__device__ __forceinline__ uint32_t smem_u32(const void* p) {
    uint32_t a;
    asm("{ .reg .u64 t; cvta.to.shared.u64 t, %1; cvt.u32.u64 %0, t; }" : "=r"(a) : "l"(p));
    return a;
}
__device__ __forceinline__ uint64_t policy_evict_last() {
    uint64_t pol;
    asm("createpolicy.fractional.L2::evict_last.b64 %0, 1.0;" : "=l"(pol));
    return pol;
}
__device__ __forceinline__ uint64_t policy_evict_first() {
    uint64_t pol;
    asm("createpolicy.fractional.L2::evict_first.b64 %0, 1.0;" : "=l"(pol));
    return pol;
}
__device__ __forceinline__ void stg_hint(float* p, float v, uint64_t pol) {
    asm volatile("st.global.L2::cache_hint.f32 [%0], %1, %2;"
                 :: "l"(p), "f"(v), "l"(pol) : "memory");
}
__device__ __forceinline__ void stg4_hint(float4* p, float4 v, uint64_t pol) {
    asm volatile("st.global.L2::cache_hint.v4.f32 [%0], {%1,%2,%3,%4}, %5;"
                 :: "l"(p), "f"(v.x), "f"(v.y), "f"(v.z), "f"(v.w), "l"(pol) : "memory");
}

// ---------------------------------------------------------------------------
// Fused kernel, per-warp double-buffered TMA pipeline.
//  blocks [0, 2256): 2 warps; each warp loops 4 tiles of 32 edges. Compute
//    tile i into buffer (i&1) while TMA drains buffer (i&1)^1
//    (wait_group.read 1). Full drain only once per warp at the end.
//  blocks [2256, 3792): embedding gather, 4 float4 per thread.
// ---------------------------------------------------------------------------
__global__ void __launch_bounds__(64) fused_kernel(
    const float*  __restrict__ pos,
    const int*    __restrict__ an,
    const float4* __restrict__ table4,
    const float*  __restrict__ alpha,
    float* __restrict__ out)
{
    __shared__ __align__(16) float buf[WPB][2][TILE_F];   // 29184 B

    if (blockIdx.x >= EDGE_BLOCKS) {
        // ---------------- embedding gather (pinned region) ----------------
        const uint64_t pol = policy_evict_last();
        const int base = (blockIdx.x - EDGE_BLOCKS) * 256 + threadIdx.x;
        float4* out4 = (float4*)(out + EMB_OFF);
#pragma unroll
        for (int it = 0; it < 4; ++it) {
            const int i = base + it * 64;            // < EMB_ITEMS
            const int n = i >> 5;
            const int c = i & 31;
            stg4_hint(out4 + i, table4[an[n] * 32 + c], pol);
        }
        return;
    }

    const int wid  = threadIdx.x >> 5;
    const int lane = threadIdx.x & 31;
    const int W    = blockIdx.x * WPB + wid;          // warp slot [0, 4512)
    const uint64_t pol_idx = policy_evict_last();

#pragma unroll
    for (int it = 0; it < T_PER_WARP; ++it) {
        const int tile = W * T_PER_WARP + it;         // [0, 18048)
        const int e    = tile * 32 + lane;

        // ---- index math ----
        const int g = e / GRAPH_E;
        const int t = e - g * GRAPH_E;
        const int s = t / (M_ATOMS - 1);
        const int k = t - s * (M_ATOMS - 1);
        const int d = k + (k >= s);
        const int src = g * M_ATOMS + s;
        const int dst = g * M_ATOMS + d;
        const int tr  = g * GRAPH_E + d * (M_ATOMS - 1) + s - (d < s);

        // ---- pos prefetch ----
        const float dx0 = __ldg(pos + dst * 3 + 0);
        const float dy0 = __ldg(pos + dst * 3 + 1);
        const float dz0 = __ldg(pos + dst * 3 + 2);
        const float sx0 = __ldg(pos + src * 3 + 0);
        const float sy0 = __ldg(pos + src * 3 + 1);
        const float sz0 = __ldg(pos + src * 3 + 2);

        // ---- index outputs (coalesced, pinned region) ----
        stg_hint(out + EI_OFF + e,         (float)dst, pol_idx);
        stg_hint(out + EI_OFF + EDGES + e, (float)src, pol_idx);
        stg_hint(out + TR_OFF + e,         (float)tr,  pol_idx);

        // ---- geometry ----
        const float ex = dx0 - sx0, ey = dy0 - sy0, ez = dz0 - sz0;
        float r2 = fmaxf(ex * ex + ey * ey + ez * ez, 1e-12f);
        const float rinv = rsqrtf(r2);          // MUFU.RSQ
        const float r    = r2 * rinv;
        const float x = ex * rinv, y = ey * rinv, z = ez * rinv;

        float* row = &buf[wid][it & 1][lane * FEAT];

        // ---- cutoff ----
        const float rc  = r * CUTOFF_INV;
        const float rc2 = rc * rc;
        const float den = fmaxf((1.0f - rc) * (1.0f + rc), 1e-9f);
        const float fcut = (rc < 1.0f) ? __expf(-__fdividef(rc2, den)) : 0.0f;

        // ---- exponential Bernstein RBF: even/odd split ratio recurrence --
        // row[v] = fcut * C(31,v) * p^(31-v) * q^v,  p = exp(xx), q = 1-p.
        // Chain from a = max(p,q) >= 1/2; direction by binomial symmetry.
        const float aeff = 0.5f * alpha[0];
        const float xx = -aeff * r;
        const float p = __expf(xx);             // MUFU.EX2
        const float q = 1.0f - p;
        const float a = fmaxf(p, q);
        const float b = 1.0f - a;
        const float ratio  = __fdividef(b, a);  // MUFU.RCP + mul
        const float ratio2 = ratio * ratio;

        const float a2 = a * a, a4 = a2 * a2, a8 = a4 * a4, a16 = a8 * a8;
        const float seed = a16 * a8 * a4 * a2 * a * fcut;   // fcut * a^31

        const bool  up   = (p >= q);
        float* sp = row + (up ? 0 : 31);
        const int step = up ? 1 : -1;

        float ev = seed;                    // term 0
        float ov = seed * (31.0f * ratio);  // term 1
        sp[0]    = ev;
        sp[step] = ov;
#pragma unroll
        for (int j = 0; j < 15; ++j) {
            const float ce = ((float)(31 - 2*j) * (float)(30 - 2*j)) /
                             ((float)(2*j + 1) * (float)(2*j + 2));
            ev *= ratio2 * ce;
            sp[step * (2*j + 2)] = ev;
            if (j < 14) {
                const float co = ((float)(30 - 2*j) * (float)(29 - 2*j)) /
                                 ((float)(2*j + 2) * (float)(2*j + 3));
                ov *= ratio2 * co;
                sp[step * (2*j + 3)] = ov;
            }
        }
        ov *= ratio2 * (2.0f / 930.0f);     // close odd chain: term 31
        sp[step * 31] = ov;

        // ---- real spherical harmonics, component-normalized, l <= 4 ----
        const float C2 = x * x - y * y,      S2 = 2.0f * x * y;
        const float C3 = C2 * x - S2 * y,    S3 = S2 * x + C2 * y;
        const float C4 = C3 * x - S3 * y,    S4 = S3 * x + C3 * y;
        const float z2 = z * z;

        const float q20 = 1.5f  * z2 - 0.5f;
        const float q30 = (2.5f * z2 - 1.5f) * z;
        const float q40 = (4.375f * z2 - 3.75f) * z2 + 0.375f;
        const float q31 = 7.5f  * z2 - 1.5f;
        const float q41 = (17.5f * z2 - 7.5f) * z;
        const float q42 = 52.5f * z2 - 7.5f;

        float* sh = row + KRBF;
        sh[0]  = 1.0f;
        sh[1]  = 1.7320508f * y;
        sh[2]  = 1.7320508f * z;
        sh[3]  = 1.7320508f * x;
        sh[4]  = 1.9364917f * S2;
        sh[5]  = 3.8729833f * y * z;
        sh[6]  = 2.2360680f * q20;
        sh[7]  = 3.8729833f * x * z;
        sh[8]  = 1.9364917f * C2;
        sh[9]  = 2.0916500f * S3;
        sh[10] = 5.1234756f * z * S2;
        sh[11] = 1.0801234f * q31 * y;
        sh[12] = 2.6457513f * q30;
        sh[13] = 1.0801234f * q31 * x;
        sh[14] = 5.1234756f * z * C2;
        sh[15] = 2.0916500f * C3;
        sh[16] = 2.2185299f * S4;
        sh[17] = 6.2749501f * z * S3;
        sh[18] = 0.2236068f * q42 * S2;
        sh[19] = 0.9486833f * q41 * y;
        sh[20] = 3.0f       * q40;
        sh[21] = 0.9486833f * q41 * x;
        sh[22] = 0.2236068f * q42 * C2;
        sh[23] = 6.2749501f * z * C3;
        sh[24] = 2.2185299f * C4;

        // ---- pipelined flush: issue TMA for this tile, wait only for the
        //      PREVIOUS tile's smem read (buffer we reuse next iteration) ----
        __syncwarp();
        if (lane == 0) {
            asm volatile("fence.proxy.async.shared::cta;" ::: "memory");
            float* gdst = out + (size_t)tile * TILE_F;
            const uint32_t saddr = smem_u32(buf[wid][it & 1]);
            const uint64_t pol = (tile < PIN_TILES) ? policy_evict_last()
                                                    : policy_evict_first();
            asm volatile(
                "cp.async.bulk.global.shared::cta.bulk_group.L2::cache_hint [%0], [%1], %2, %3;"
                :: "l"(gdst), "r"(saddr), "r"(TILE_F * 4), "l"(pol) : "memory");
            asm volatile("cp.async.bulk.commit_group;" ::: "memory");
            asm volatile("cp.async.bulk.wait_group.read 1;" ::: "memory");
        }
        __syncwarp();   // buffer (it&1)^1 is now safe to overwrite next iter
    }

    // final drain before CTA retires (smem must stay valid until TMA reads)
    if (lane == 0)
        asm volatile("cp.async.bulk.wait_group.read 0;" ::: "memory");
}

extern "C" void kernel_launch(void* const* d_in, const int* in_sizes, int n_in,
                              void* d_out, int out_size)
{
    const float* pos   = (const float*)d_in[0];
    const int*   an    = (const int*)d_in[1];
    const float* table = (const float*)d_in[2];
    const float* alpha = (const float*)d_in[3];
    float* out = (float*)d_out;

    fused_kernel<<<TOTAL_BLOCKS, 64>>>(pos, an, (const float4*)table, alpha, out);
}